// round 4
// baseline (speedup 1.0000x reference)
#include <cuda_runtime.h>
#include <math.h>

#define NN   100000
#define EE   3200000
#define IND  128
#define H1D  32
#define H2D  64
#define H3D  10
#define NBLK 391          // ceil(NN/256)

typedef unsigned long long ull;

// ---------------- scratch (device globals; no allocations allowed) ----------
__device__ float g_t[NN * H1D];       // (x @ W_shared) * dis  (row-scaled)
__device__ float g_h[NN * H1D];       // dis * relu'd layer-1  (row-scaled)
__device__ float g_agg[NN * H1D];     // second aggregation result (true agg)
__device__ int   g_cnt[NN];           // per-dst edge counts (no self loop)
__device__ float g_dis[NN];           // (deg+1)^-1/2
__device__ int   g_ptr[NN];           // CSR row starts (exclusive)
__device__ int   g_cur[NN];           // fill cursors
__device__ int   g_bsum[512];         // scan block sums
__device__ int   g_esrc[EE];          // CSR: src node per slot (4B records)
__device__ int2  g_e32[EE];           // packed (s,d) int32 per original edge
__device__ __align__(128) float g_d2p[NN * 32];  // padded 128B records:
                                      // c @ [0:10), zeros [10:12); n @ [16:26), zeros [26:28)
__device__ int g_is64;

// ---------------- f32x2 helpers (sm_103a packed fp32) ----------------------
__device__ __forceinline__ ull pack2(float lo, float hi) {
    ull r; asm("mov.b64 %0,{%1,%2};" : "=l"(r) : "f"(lo), "f"(hi)); return r;
}
__device__ __forceinline__ ull fma2(ull a, ull b, ull c) {
    ull d; asm("fma.rn.f32x2 %0,%1,%2,%3;" : "=l"(d) : "l"(a), "l"(b), "l"(c)); return d;
}
__device__ __forceinline__ void unpack2(ull v, float& lo, float& hi) {
    asm("mov.b64 {%0,%1},%2;" : "=f"(lo), "=f"(hi) : "l"(v));
}
__device__ __forceinline__ float ftanh(float x) {
    float e = __expf(2.0f * x);               // inf-safe
    return 1.0f - __fdividef(2.0f, e + 1.0f);
}

__device__ __forceinline__ int eidx(const int* __restrict__ w, long long pos, int is64) {
    return is64 ? w[2 * pos] : w[pos];
}

// Detect int64 vs int32 edge_index + zero counts (fused).
__global__ void k_boot(const int* __restrict__ w) {
    int i = blockIdx.x * 256 + threadIdx.x;
    if (i < NN) g_cnt[i] = 0;
    if (i == 0) {
        int all0 = 1;
        for (int q = 0; q < 16; q++)
            if (w[2 * q + 1] != 0) all0 = 0;
        g_is64 = all0;
    }
}

// Count degrees AND convert edge_index to packed int32 pairs (one int64 pass).
__global__ void k_deg(const int* __restrict__ ew) {
    int e = blockIdx.x * blockDim.x + threadIdx.x;
    if (e >= EE) return;
    int is64 = g_is64;
    int s = eidx(ew, e, is64);
    int d = eidx(ew, (long long)EE + e, is64);
    g_e32[e] = make_int2(s, d);
    atomicAdd(&g_cnt[d], 1);
}

// ---- 3-phase exclusive prefix scan of g_cnt into g_ptr (+ dis fused) ----
__global__ void k_scan1() {
    __shared__ int s[256];
    int i = blockIdx.x * 256 + threadIdx.x;
    int v = (i < NN) ? g_cnt[i] : 0;
    if (i < NN) g_dis[i] = rsqrtf((float)v + 1.0f);
    s[threadIdx.x] = v;
    __syncthreads();
    for (int o = 1; o < 256; o <<= 1) {
        int t = (threadIdx.x >= o) ? s[threadIdx.x - o] : 0;
        __syncthreads();
        s[threadIdx.x] += t;
        __syncthreads();
    }
    if (i < NN) g_ptr[i] = s[threadIdx.x];
    if (threadIdx.x == 255) g_bsum[blockIdx.x] = s[255];
}

__global__ void k_scan2() {
    __shared__ int s[512];
    int tid = threadIdx.x;
    int v = (tid < NBLK) ? g_bsum[tid] : 0;
    s[tid] = v;
    __syncthreads();
    for (int o = 1; o < 512; o <<= 1) {
        int t = (tid >= o) ? s[tid - o] : 0;
        __syncthreads();
        s[tid] += t;
        __syncthreads();
    }
    g_bsum[tid] = s[tid] - v;
}

__global__ void k_scan3() {
    int i = blockIdx.x * 256 + threadIdx.x;
    if (i >= NN) return;
    int start = g_ptr[i] + g_bsum[i >> 8] - g_cnt[i];
    g_ptr[i] = start;
    g_cur[i] = start;
}

// Scatter edges into CSR slots: bare 4B src record (norm factored out).
__global__ void k_fill() {
    int e = blockIdx.x * blockDim.x + threadIdx.x;
    if (e >= EE) return;
    int2 sd = g_e32[e];
    int pos = atomicAdd(&g_cur[sd.y], 1);
    g_esrc[pos] = sd.x;
}

// t' = (x @ W_shared) * dis[row].  Warp per 4 rows, W in smem.
__global__ void k_gemm1(const float* __restrict__ x, const float* __restrict__ W) {
    __shared__ float Ws[IND * H1D];
    int tid = threadIdx.x;
    for (int i = tid; i < IND * H1D; i += 256) Ws[i] = W[i];
    __syncthreads();

    int gw = (blockIdx.x * 256 + tid) >> 5;
    int lane = tid & 31;
    int row0 = gw * 4;
    if (row0 >= NN) return;

    float xv[4][4];
#pragma unroll
    for (int rr = 0; rr < 4; rr++) {
        const float* xr = x + (size_t)(row0 + rr) * IND;
#pragma unroll
        for (int u = 0; u < 4; u++) xv[rr][u] = xr[u * 32 + lane];
    }
    float acc[4] = {0.f, 0.f, 0.f, 0.f};
#pragma unroll
    for (int u = 0; u < 4; u++) {
#pragma unroll 8
        for (int k2 = 0; k2 < 32; k2++) {
            float w = Ws[(u * 32 + k2) * H1D + lane];
#pragma unroll
            for (int rr = 0; rr < 4; rr++)
                acc[rr] += __shfl_sync(0xffffffffu, xv[rr][u], k2) * w;
        }
    }
#pragma unroll
    for (int rr = 0; rr < 4; rr++)
        g_t[(size_t)(row0 + rr) * H1D + lane] = acc[rr] * g_dis[row0 + rr];
}

// CSR gather aggregation on row-scaled inputs: pure adds, no per-edge norm.
// mode 0: t' -> h' = dis*relu(dis*(sum+t'[self]) + b)
// mode 1: h' -> agg = dis*(sum + h'[self])
__global__ void k_aggcsr(const float* __restrict__ b, int mode) {
    __shared__ int sE[8][32];
    const float* __restrict__ src = mode ? g_h : g_t;
    int lane = threadIdx.x & 31;
    int w = threadIdx.x >> 5;
    int node = (blockIdx.x * blockDim.x + threadIdx.x) >> 5;
    if (node >= NN) return;

    int j = g_ptr[node];
    int rem = g_cnt[node];
    float dd = g_dis[node];
    float acc0 = src[(size_t)node * H1D + lane];  // self term (already scaled)
    float acc1 = 0.f;

    while (rem >= 32) {
        sE[w][lane] = g_esrc[j + lane];
        __syncwarp();
#pragma unroll
        for (int q = 0; q < 32; q += 2) {
            acc0 += src[(size_t)sE[w][q] * H1D + lane];
            acc1 += src[(size_t)sE[w][q + 1] * H1D + lane];
        }
        __syncwarp();
        j += 32;
        rem -= 32;
    }
    if (rem > 0) {
        if (lane < rem) sE[w][lane] = g_esrc[j + lane];
        __syncwarp();
        for (int q = 0; q < rem; q++)
            acc0 += src[(size_t)sE[w][q] * H1D + lane];
    }
    float acc = acc0 + acc1;

    if (mode == 0) {
        float v = dd * acc + b[lane];
        g_h[(size_t)node * H1D + lane] = dd * (v > 0.f ? v : 0.f);
    } else {
        g_agg[(size_t)node * H1D + lane] = dd * acc;
    }
}

// Fused per-node tail: agg -> (mu,lv)x2 -> z -> decoder d1 -> d2.
// Broadcast operands staged in smem (LDS.64 broadcast) instead of SHFL chains.
__global__ void k_mlp(
    const float* __restrict__ eps_c, const float* __restrict__ eps_n,
    const float* __restrict__ Wmc, const float* __restrict__ bmc,
    const float* __restrict__ Wmn, const float* __restrict__ bmn,
    const float* __restrict__ Wlc, const float* __restrict__ blc,
    const float* __restrict__ Wln, const float* __restrict__ bln,
    const float* __restrict__ Wd1c, const float* __restrict__ bd1c,
    const float* __restrict__ Wd2c, const float* __restrict__ bd2c,
    const float* __restrict__ Wd1n, const float* __restrict__ bd1n,
    const float* __restrict__ Wd2n, const float* __restrict__ bd2n,
    float* __restrict__ omc, float* __restrict__ omn,
    float* __restrict__ olc, float* __restrict__ oln) {
    __shared__ ull sWp[4][H1D * 32];    // mu_c, lv_c, mu_n, lv_n packed pairs
    __shared__ ull sD1p[2][32 * 32];    // decoder-1 packed (k, k+32)
    __shared__ ull sD2p[2][16 * H3D];   // decoder-2 packed (2kp, 2kp+1)
    __shared__ ull sA[8][4 * 32];       // splat2(a[rr][k]) per warp
    __shared__ ull sZ[8][32];           // pack2(z0,z1) per warp, per row
    __shared__ float sDv[8][32];        // d1 values per warp, per row

    int tid = threadIdx.x;
    for (int i = tid; i < 1024; i += 256) {
        int k = i >> 5, lane = i & 31;
        sWp[0][i] = pack2(Wmc[k * 64 + lane], Wmc[k * 64 + lane + 32]);
        sWp[1][i] = pack2(Wlc[k * 64 + lane], Wlc[k * 64 + lane + 32]);
        sWp[2][i] = pack2(Wmn[k * 64 + lane], Wmn[k * 64 + lane + 32]);
        sWp[3][i] = pack2(Wln[k * 64 + lane], Wln[k * 64 + lane + 32]);
        sD1p[0][i] = pack2(Wd1c[k * 32 + lane], Wd1c[(k + 32) * 32 + lane]);
        sD1p[1][i] = pack2(Wd1n[k * 32 + lane], Wd1n[(k + 32) * 32 + lane]);
    }
    for (int i = tid; i < 16 * H3D; i += 256) {
        int kp = i / H3D, j = i % H3D;
        sD2p[0][i] = pack2(Wd2c[(2 * kp) * H3D + j], Wd2c[(2 * kp + 1) * H3D + j]);
        sD2p[1][i] = pack2(Wd2n[(2 * kp) * H3D + j], Wd2n[(2 * kp + 1) * H3D + j]);
    }
    __syncthreads();

    int lane = tid & 31;
    int warp = tid >> 5;
    int row0 = (blockIdx.x * 8 + warp) * 4;
    if (row0 >= NN) return;

#pragma unroll
    for (int rr = 0; rr < 4; rr++) {
        float a = g_agg[(size_t)(row0 + rr) * H1D + lane];
        sA[warp][rr * 32 + lane] = pack2(a, a);
    }
    __syncwarp();

    int jj = lane < H3D ? lane : 0;

#pragma unroll
    for (int half = 0; half < 2; half++) {   // 0: causal, 1: non-causal
        const ull* Wm = sWp[half * 2];
        const ull* Wl = sWp[half * 2 + 1];
        const ull* D1 = sD1p[half];
        const ull* D2 = sD2p[half];
        const float* bm = half ? bmn : bmc;
        const float* bl = half ? bln : blc;
        const float* b1 = half ? bd1n : bd1c;
        const float* b2 = half ? bd2n : bd2c;
        const float* eps = half ? eps_n : eps_c;
        float* om = half ? omn : omc;
        float* ol = half ? oln : olc;

        ull m01[4], l01[4];
        {
            ull bmp = pack2(bm[lane], bm[lane + 32]);
            ull blp = pack2(bl[lane], bl[lane + 32]);
#pragma unroll
            for (int rr = 0; rr < 4; rr++) { m01[rr] = bmp; l01[rr] = blp; }
        }
#pragma unroll 8
        for (int k = 0; k < 32; k++) {
            ull wm = Wm[k * 32 + lane];
            ull wl = Wl[k * 32 + lane];
#pragma unroll
            for (int rr = 0; rr < 4; rr++) {
                ull a2 = sA[warp][rr * 32 + k];
                m01[rr] = fma2(a2, wm, m01[rr]);
                l01[rr] = fma2(a2, wl, l01[rr]);
            }
        }

        float z0[4], z1[4];
#pragma unroll
        for (int rr = 0; rr < 4; rr++) {
            size_t i = row0 + rr;
            float m0, m1, l0, l1;
            unpack2(m01[rr], m0, m1);
            unpack2(l01[rr], l0, l1);
            om[i * H2D + lane] = m0;
            om[i * H2D + lane + 32] = m1;
            ol[i * H2D + lane] = l0;
            ol[i * H2D + lane + 32] = l1;
            z0[rr] = m0 + eps[i * H2D + lane] * __expf(0.5f * l0);
            z1[rr] = m1 + eps[i * H2D + lane + 32] * __expf(0.5f * l1);
        }

        float b1v = b1[lane];
        float b2v = b2[jj];
#pragma unroll
        for (int rr = 0; rr < 4; rr++) {
            size_t i = row0 + rr;
            sZ[warp][lane] = pack2(z0[rr], z1[rr]);
            __syncwarp();
            ull acc1 = pack2(b1v, 0.f);
#pragma unroll 8
            for (int k = 0; k < 32; k++)
                acc1 = fma2(sZ[warp][k], D1[k * 32 + lane], acc1);
            float s0, s1;
            unpack2(acc1, s0, s1);
            float d1 = ftanh(s0 + s1);
            sDv[warp][lane] = d1;
            __syncwarp();
            ull acc2 = pack2(b2v, 0.f);
#pragma unroll 8
            for (int kp = 0; kp < 16; kp++) {
                ull dp = *reinterpret_cast<const ull*>(&sDv[warp][2 * kp]);
                acc2 = fma2(dp, D2[kp * H3D + jj], acc2);
            }
            unpack2(acc2, s0, s1);
            float v = ftanh(s0 + s1);
            // padded record: half 0 -> floats [0:12), half 1 -> [16:28)
            if (lane < 12)
                g_d2p[i * 32 + half * 16 + lane] = (lane < H3D) ? v : 0.f;
            __syncwarp();
        }
    }
}

// Warp-cooperative decode: 2 edges (4 node records) per LDG.128 instruction.
// Record = 128B aligned; lanes r=lane>>3 pick record, q=lane&7 pick float4.
// q==3 / q==7 predicated off (only 6 sectors fetched per record).
__global__ void k_decode(float* __restrict__ oc, float* __restrict__ on) {
    __shared__ float s_oc[8][32], s_on[8][32];
    int tid = threadIdx.x;
    int w = tid >> 5, lane = tid & 31;
    int chunk = (blockIdx.x * 8 + w) * 32;
    if (chunk >= EE) return;

    int r = lane >> 3, q = lane & 7;
    bool qok = (q & 3) != 3;
    int rodd = r & 1, rhi = r >> 1;
    int2 myE = g_e32[chunk + lane];

#pragma unroll
    for (int it = 0; it < 16; it++) {
        int sl = 2 * it + rhi;
        int nx = __shfl_sync(0xffffffffu, myE.x, sl);
        int ny = __shfl_sync(0xffffffffu, myE.y, sl);
        int node = rodd ? ny : nx;
        float4 v = make_float4(0.f, 0.f, 0.f, 0.f);
        if (qok)
            v = *reinterpret_cast<const float4*>(g_d2p + (size_t)node * 32 + q * 4);
        float px = __shfl_xor_sync(0xffffffffu, v.x, 8);
        float py = __shfl_xor_sync(0xffffffffu, v.y, 8);
        float pz = __shfl_xor_sync(0xffffffffu, v.z, 8);
        float pw = __shfl_xor_sync(0xffffffffu, v.w, 8);
        float loc = v.x * px + v.y * py + v.z * pz + v.w * pw;
        loc += __shfl_xor_sync(0xffffffffu, loc, 1);
        loc += __shfl_xor_sync(0xffffffffu, loc, 2);
        // lanes q0..3 hold c-sum, q4..7 hold n-sum (r0/r1 = edge A, r2/r3 = edge B)
        if (lane == 0 || lane == 16) s_oc[w][2 * it + (lane >> 4)] = loc;
        if (lane == 4 || lane == 20) s_on[w][2 * it + (lane >> 4)] = loc;
    }
    __syncwarp();
    float c = s_oc[w][lane];
    float n = s_on[w][lane];
    oc[chunk + lane] = __fdividef(1.f, 1.f + __expf(-c));
    on[chunk + lane] = __fdividef(1.f, 1.f + __expf(-n));
}

extern "C" void kernel_launch(void* const* d_in, const int* in_sizes, int n_in,
                              void* d_out, int out_size) {
    const float* x        = (const float*)d_in[0];
    const int*   ew       = (const int*)d_in[1];
    const float* eps_c    = (const float*)d_in[2];
    const float* eps_n    = (const float*)d_in[3];
    const float* W_shared = (const float*)d_in[4];
    const float* b_shared = (const float*)d_in[5];
    const float* Wmc = (const float*)d_in[6],  *bmc = (const float*)d_in[7];
    const float* Wmn = (const float*)d_in[8],  *bmn = (const float*)d_in[9];
    const float* Wlc = (const float*)d_in[10], *blc = (const float*)d_in[11];
    const float* Wln = (const float*)d_in[12], *bln = (const float*)d_in[13];
    const float* Wd1c = (const float*)d_in[14], *bd1c = (const float*)d_in[15];
    const float* Wd2c = (const float*)d_in[16], *bd2c = (const float*)d_in[17];
    const float* Wd1n = (const float*)d_in[18], *bd1n = (const float*)d_in[19];
    const float* Wd2n = (const float*)d_in[20], *bd2n = (const float*)d_in[21];

    float* out  = (float*)d_out;
    float* oewc = out;
    float* oewn = out + (size_t)EE;
    float* omc  = out + 2 * (size_t)EE;
    float* omn  = omc + (size_t)NN * H2D;
    float* olc  = omn + (size_t)NN * H2D;
    float* oln  = olc + (size_t)NN * H2D;

    k_boot<<<NBLK, 256>>>(ew);
    k_deg<<<(EE + 255) / 256, 256>>>(ew);
    k_scan1<<<NBLK, 256>>>();
    k_scan2<<<1, 512>>>();
    k_scan3<<<NBLK, 256>>>();
    k_fill<<<(EE + 255) / 256, 256>>>();
    k_gemm1<<<(NN / 4 + 7) / 8, 256>>>(x, W_shared);
    k_aggcsr<<<(NN + 7) / 8, 256>>>(b_shared, 0);   // t' -> h'
    k_aggcsr<<<(NN + 7) / 8, 256>>>(nullptr, 1);    // h' -> agg
    k_mlp<<<NN / 32, 256>>>(eps_c, eps_n, Wmc, bmc, Wmn, bmn, Wlc, blc, Wln, bln,
                            Wd1c, bd1c, Wd2c, bd2c, Wd1n, bd1n, Wd2n, bd2n,
                            omc, omn, olc, oln);
    k_decode<<<(EE / 32 + 7) / 8, 256>>>(oewc, oewn);
}

// round 5
// speedup vs baseline: 1.2751x; 1.2751x over previous
#include <cuda_runtime.h>
#include <math.h>

#define NN   100000
#define EE   3200000
#define IND  128
#define H1D  32
#define H2D  64
#define H3D  10
#define NBLK 391          // ceil(NN/256)

typedef unsigned long long ull;

// ---------------- scratch (device globals; no allocations allowed) ----------
__device__ float g_t[NN * H1D];       // (x @ W_shared) * dis  (row-scaled)
__device__ float g_h[NN * H1D];       // dis * relu'd layer-1  (row-scaled)
__device__ float g_agg[NN * H1D];     // second aggregation result (true agg)
__device__ int   g_cnt[NN];           // per-dst edge counts (no self loop)
__device__ float g_dis[NN];           // (deg+1)^-1/2
__device__ int   g_ptr[NN];           // CSR row starts (exclusive)
__device__ int   g_cur[NN];           // fill cursors
__device__ int   g_bsum[512];         // scan block sums
__device__ int   g_esrc[EE];          // CSR: src node per slot (4B records)
__device__ int2  g_e32[EE];           // packed (s,d) int32 per original edge
__device__ __align__(16) float g_d2[NN * 20];  // dense records: c[0:10) | n[10:20)
__device__ int g_is64;

// ---------------- f32x2 helpers (sm_103a packed fp32) ----------------------
__device__ __forceinline__ ull pack2(float lo, float hi) {
    ull r; asm("mov.b64 %0,{%1,%2};" : "=l"(r) : "f"(lo), "f"(hi)); return r;
}
__device__ __forceinline__ ull fma2(ull a, ull b, ull c) {
    ull d; asm("fma.rn.f32x2 %0,%1,%2,%3;" : "=l"(d) : "l"(a), "l"(b), "l"(c)); return d;
}
__device__ __forceinline__ void unpack2(ull v, float& lo, float& hi) {
    asm("mov.b64 {%0,%1},%2;" : "=f"(lo), "=f"(hi) : "l"(v));
}
__device__ __forceinline__ float ftanh(float x) {
    float e = __expf(2.0f * x);               // inf-safe
    return 1.0f - __fdividef(2.0f, e + 1.0f);
}

__device__ __forceinline__ int eidx(const int* __restrict__ w, long long pos, int is64) {
    return is64 ? w[2 * pos] : w[pos];
}

// Detect int64 vs int32 edge_index + zero counts (fused).
__global__ void k_boot(const int* __restrict__ w) {
    int i = blockIdx.x * 256 + threadIdx.x;
    if (i < NN) g_cnt[i] = 0;
    if (i == 0) {
        int all0 = 1;
        for (int q = 0; q < 16; q++)
            if (w[2 * q + 1] != 0) all0 = 0;
        g_is64 = all0;
    }
}

// Count degrees AND convert edge_index to packed int32 pairs (one int64 pass).
__global__ void k_deg(const int* __restrict__ ew) {
    int e = blockIdx.x * blockDim.x + threadIdx.x;
    if (e >= EE) return;
    int is64 = g_is64;
    int s = eidx(ew, e, is64);
    int d = eidx(ew, (long long)EE + e, is64);
    g_e32[e] = make_int2(s, d);
    atomicAdd(&g_cnt[d], 1);
}

// ---- 3-phase exclusive prefix scan of g_cnt into g_ptr (+ dis fused) ----
__global__ void k_scan1() {
    __shared__ int s[256];
    int i = blockIdx.x * 256 + threadIdx.x;
    int v = (i < NN) ? g_cnt[i] : 0;
    if (i < NN) g_dis[i] = rsqrtf((float)v + 1.0f);
    s[threadIdx.x] = v;
    __syncthreads();
    for (int o = 1; o < 256; o <<= 1) {
        int t = (threadIdx.x >= o) ? s[threadIdx.x - o] : 0;
        __syncthreads();
        s[threadIdx.x] += t;
        __syncthreads();
    }
    if (i < NN) g_ptr[i] = s[threadIdx.x];
    if (threadIdx.x == 255) g_bsum[blockIdx.x] = s[255];
}

__global__ void k_scan2() {
    __shared__ int s[512];
    int tid = threadIdx.x;
    int v = (tid < NBLK) ? g_bsum[tid] : 0;
    s[tid] = v;
    __syncthreads();
    for (int o = 1; o < 512; o <<= 1) {
        int t = (tid >= o) ? s[tid - o] : 0;
        __syncthreads();
        s[tid] += t;
        __syncthreads();
    }
    g_bsum[tid] = s[tid] - v;
}

__global__ void k_scan3() {
    int i = blockIdx.x * 256 + threadIdx.x;
    if (i >= NN) return;
    int start = g_ptr[i] + g_bsum[i >> 8] - g_cnt[i];
    g_ptr[i] = start;
    g_cur[i] = start;
}

// Scatter edges into CSR slots: bare 4B src record (norm factored out).
__global__ void k_fill() {
    int e = blockIdx.x * blockDim.x + threadIdx.x;
    if (e >= EE) return;
    int2 sd = g_e32[e];
    int pos = atomicAdd(&g_cur[sd.y], 1);
    g_esrc[pos] = sd.x;
}

// t' = (x @ W_shared) * dis[row].  Warp per 4 rows, W in smem.
__global__ void k_gemm1(const float* __restrict__ x, const float* __restrict__ W) {
    __shared__ float Ws[IND * H1D];
    int tid = threadIdx.x;
    for (int i = tid; i < IND * H1D; i += 256) Ws[i] = W[i];
    __syncthreads();

    int gw = (blockIdx.x * 256 + tid) >> 5;
    int lane = tid & 31;
    int row0 = gw * 4;
    if (row0 >= NN) return;

    float xv[4][4];
#pragma unroll
    for (int rr = 0; rr < 4; rr++) {
        const float* xr = x + (size_t)(row0 + rr) * IND;
#pragma unroll
        for (int u = 0; u < 4; u++) xv[rr][u] = xr[u * 32 + lane];
    }
    float acc[4] = {0.f, 0.f, 0.f, 0.f};
#pragma unroll
    for (int u = 0; u < 4; u++) {
#pragma unroll 8
        for (int k2 = 0; k2 < 32; k2++) {
            float w = Ws[(u * 32 + k2) * H1D + lane];
#pragma unroll
            for (int rr = 0; rr < 4; rr++)
                acc[rr] += __shfl_sync(0xffffffffu, xv[rr][u], k2) * w;
        }
    }
#pragma unroll
    for (int rr = 0; rr < 4; rr++)
        g_t[(size_t)(row0 + rr) * H1D + lane] = acc[rr] * g_dis[row0 + rr];
}

// CSR gather aggregation on row-scaled inputs: pure adds, no per-edge norm.
// mode 0: t' -> h' = dis*relu(dis*(sum+t'[self]) + b)
// mode 1: h' -> agg = dis*(sum + h'[self])
__global__ void k_aggcsr(const float* __restrict__ b, int mode) {
    __shared__ int sE[8][32];
    const float* __restrict__ src = mode ? g_h : g_t;
    int lane = threadIdx.x & 31;
    int w = threadIdx.x >> 5;
    int node = (blockIdx.x * blockDim.x + threadIdx.x) >> 5;
    if (node >= NN) return;

    int j = g_ptr[node];
    int rem = g_cnt[node];
    float dd = g_dis[node];
    float acc0 = src[(size_t)node * H1D + lane];  // self term (already scaled)
    float acc1 = 0.f;

    while (rem >= 32) {
        sE[w][lane] = g_esrc[j + lane];
        __syncwarp();
#pragma unroll
        for (int q = 0; q < 32; q += 2) {
            acc0 += src[(size_t)sE[w][q] * H1D + lane];
            acc1 += src[(size_t)sE[w][q + 1] * H1D + lane];
        }
        __syncwarp();
        j += 32;
        rem -= 32;
    }
    if (rem > 0) {
        if (lane < rem) sE[w][lane] = g_esrc[j + lane];
        __syncwarp();
        for (int q = 0; q < rem; q++)
            acc0 += src[(size_t)sE[w][q] * H1D + lane];
    }
    float acc = acc0 + acc1;

    if (mode == 0) {
        float v = dd * acc + b[lane];
        g_h[(size_t)node * H1D + lane] = dd * (v > 0.f ? v : 0.f);
    } else {
        g_agg[(size_t)node * H1D + lane] = dd * acc;
    }
}

// Fused per-node tail: agg -> (mu,lv)x2 -> z -> decoder d1 -> d2.
// Broadcast operands staged in smem (LDS.64 broadcast) instead of SHFL chains.
__global__ void k_mlp(
    const float* __restrict__ eps_c, const float* __restrict__ eps_n,
    const float* __restrict__ Wmc, const float* __restrict__ bmc,
    const float* __restrict__ Wmn, const float* __restrict__ bmn,
    const float* __restrict__ Wlc, const float* __restrict__ blc,
    const float* __restrict__ Wln, const float* __restrict__ bln,
    const float* __restrict__ Wd1c, const float* __restrict__ bd1c,
    const float* __restrict__ Wd2c, const float* __restrict__ bd2c,
    const float* __restrict__ Wd1n, const float* __restrict__ bd1n,
    const float* __restrict__ Wd2n, const float* __restrict__ bd2n,
    float* __restrict__ omc, float* __restrict__ omn,
    float* __restrict__ olc, float* __restrict__ oln) {
    __shared__ ull sWp[4][H1D * 32];    // mu_c, lv_c, mu_n, lv_n packed pairs
    __shared__ ull sD1p[2][32 * 32];    // decoder-1 packed (k, k+32)
    __shared__ ull sD2p[2][16 * H3D];   // decoder-2 packed (2kp, 2kp+1)
    __shared__ ull sA[8][4 * 32];       // splat2(a[rr][k]) per warp
    __shared__ ull sZ[8][32];           // pack2(z0,z1) per warp, per row
    __shared__ float sDv[8][32];        // d1 values per warp, per row

    int tid = threadIdx.x;
    for (int i = tid; i < 1024; i += 256) {
        int k = i >> 5, lane = i & 31;
        sWp[0][i] = pack2(Wmc[k * 64 + lane], Wmc[k * 64 + lane + 32]);
        sWp[1][i] = pack2(Wlc[k * 64 + lane], Wlc[k * 64 + lane + 32]);
        sWp[2][i] = pack2(Wmn[k * 64 + lane], Wmn[k * 64 + lane + 32]);
        sWp[3][i] = pack2(Wln[k * 64 + lane], Wln[k * 64 + lane + 32]);
        sD1p[0][i] = pack2(Wd1c[k * 32 + lane], Wd1c[(k + 32) * 32 + lane]);
        sD1p[1][i] = pack2(Wd1n[k * 32 + lane], Wd1n[(k + 32) * 32 + lane]);
    }
    for (int i = tid; i < 16 * H3D; i += 256) {
        int kp = i / H3D, j = i % H3D;
        sD2p[0][i] = pack2(Wd2c[(2 * kp) * H3D + j], Wd2c[(2 * kp + 1) * H3D + j]);
        sD2p[1][i] = pack2(Wd2n[(2 * kp) * H3D + j], Wd2n[(2 * kp + 1) * H3D + j]);
    }
    __syncthreads();

    int lane = tid & 31;
    int warp = tid >> 5;
    int row0 = (blockIdx.x * 8 + warp) * 4;
    if (row0 >= NN) return;

#pragma unroll
    for (int rr = 0; rr < 4; rr++) {
        float a = g_agg[(size_t)(row0 + rr) * H1D + lane];
        sA[warp][rr * 32 + lane] = pack2(a, a);
    }
    __syncwarp();

    int jj = lane < H3D ? lane : 0;

#pragma unroll
    for (int half = 0; half < 2; half++) {   // 0: causal, 1: non-causal
        const ull* Wm = sWp[half * 2];
        const ull* Wl = sWp[half * 2 + 1];
        const ull* D1 = sD1p[half];
        const ull* D2 = sD2p[half];
        const float* bm = half ? bmn : bmc;
        const float* bl = half ? bln : blc;
        const float* b1 = half ? bd1n : bd1c;
        const float* b2 = half ? bd2n : bd2c;
        const float* eps = half ? eps_n : eps_c;
        float* om = half ? omn : omc;
        float* ol = half ? oln : olc;

        ull m01[4], l01[4];
        {
            ull bmp = pack2(bm[lane], bm[lane + 32]);
            ull blp = pack2(bl[lane], bl[lane + 32]);
#pragma unroll
            for (int rr = 0; rr < 4; rr++) { m01[rr] = bmp; l01[rr] = blp; }
        }
#pragma unroll 8
        for (int k = 0; k < 32; k++) {
            ull wm = Wm[k * 32 + lane];
            ull wl = Wl[k * 32 + lane];
#pragma unroll
            for (int rr = 0; rr < 4; rr++) {
                ull a2 = sA[warp][rr * 32 + k];
                m01[rr] = fma2(a2, wm, m01[rr]);
                l01[rr] = fma2(a2, wl, l01[rr]);
            }
        }

        float z0[4], z1[4];
#pragma unroll
        for (int rr = 0; rr < 4; rr++) {
            size_t i = row0 + rr;
            float m0, m1, l0, l1;
            unpack2(m01[rr], m0, m1);
            unpack2(l01[rr], l0, l1);
            om[i * H2D + lane] = m0;
            om[i * H2D + lane + 32] = m1;
            ol[i * H2D + lane] = l0;
            ol[i * H2D + lane + 32] = l1;
            z0[rr] = m0 + eps[i * H2D + lane] * __expf(0.5f * l0);
            z1[rr] = m1 + eps[i * H2D + lane + 32] * __expf(0.5f * l1);
        }

        float b1v = b1[lane];
        float b2v = b2[jj];
#pragma unroll
        for (int rr = 0; rr < 4; rr++) {
            size_t i = row0 + rr;
            sZ[warp][lane] = pack2(z0[rr], z1[rr]);
            __syncwarp();
            ull acc1 = pack2(b1v, 0.f);
#pragma unroll 8
            for (int k = 0; k < 32; k++)
                acc1 = fma2(sZ[warp][k], D1[k * 32 + lane], acc1);
            float s0, s1;
            unpack2(acc1, s0, s1);
            float d1 = ftanh(s0 + s1);
            sDv[warp][lane] = d1;
            __syncwarp();
            ull acc2 = pack2(b2v, 0.f);
#pragma unroll 8
            for (int kp = 0; kp < 16; kp++) {
                ull dp = *reinterpret_cast<const ull*>(&sDv[warp][2 * kp]);
                acc2 = fma2(dp, D2[kp * H3D + jj], acc2);
            }
            unpack2(acc2, s0, s1);
            float v = ftanh(s0 + s1);
            if (lane < H3D) g_d2[i * 20 + half * H3D + lane] = v;
            __syncwarp();
        }
    }
}

// Per-edge inner products + sigmoid, both decoders in one pass. Dense 80B records.
__global__ void k_decode(float* __restrict__ oc, float* __restrict__ on) {
    int e = blockIdx.x * blockDim.x + threadIdx.x;
    if (e >= EE) return;
    int2 sd = g_e32[e];

    const float4* pa = reinterpret_cast<const float4*>(g_d2 + (size_t)sd.x * 20);
    const float4* pb = reinterpret_cast<const float4*>(g_d2 + (size_t)sd.y * 20);
    float4 a0 = pa[0], a1 = pa[1], a2 = pa[2], a3 = pa[3], a4 = pa[4];
    float4 b0 = pb[0], b1 = pb[1], b2 = pb[2], b3 = pb[3], b4 = pb[4];

    float accc = a0.x * b0.x + a0.y * b0.y + a0.z * b0.z + a0.w * b0.w
               + a1.x * b1.x + a1.y * b1.y + a1.z * b1.z + a1.w * b1.w
               + a2.x * b2.x + a2.y * b2.y;
    float accn = a2.z * b2.z + a2.w * b2.w
               + a3.x * b3.x + a3.y * b3.y + a3.z * b3.z + a3.w * b3.w
               + a4.x * b4.x + a4.y * b4.y + a4.z * b4.z + a4.w * b4.w;
    oc[e] = __fdividef(1.f, 1.f + __expf(-accc));
    on[e] = __fdividef(1.f, 1.f + __expf(-accn));
}

extern "C" void kernel_launch(void* const* d_in, const int* in_sizes, int n_in,
                              void* d_out, int out_size) {
    const float* x        = (const float*)d_in[0];
    const int*   ew       = (const int*)d_in[1];
    const float* eps_c    = (const float*)d_in[2];
    const float* eps_n    = (const float*)d_in[3];
    const float* W_shared = (const float*)d_in[4];
    const float* b_shared = (const float*)d_in[5];
    const float* Wmc = (const float*)d_in[6],  *bmc = (const float*)d_in[7];
    const float* Wmn = (const float*)d_in[8],  *bmn = (const float*)d_in[9];
    const float* Wlc = (const float*)d_in[10], *blc = (const float*)d_in[11];
    const float* Wln = (const float*)d_in[12], *bln = (const float*)d_in[13];
    const float* Wd1c = (const float*)d_in[14], *bd1c = (const float*)d_in[15];
    const float* Wd2c = (const float*)d_in[16], *bd2c = (const float*)d_in[17];
    const float* Wd1n = (const float*)d_in[18], *bd1n = (const float*)d_in[19];
    const float* Wd2n = (const float*)d_in[20], *bd2n = (const float*)d_in[21];

    float* out  = (float*)d_out;
    float* oewc = out;
    float* oewn = out + (size_t)EE;
    float* omc  = out + 2 * (size_t)EE;
    float* omn  = omc + (size_t)NN * H2D;
    float* olc  = omn + (size_t)NN * H2D;
    float* oln  = olc + (size_t)NN * H2D;

    k_boot<<<NBLK, 256>>>(ew);
    k_deg<<<(EE + 255) / 256, 256>>>(ew);
    k_scan1<<<NBLK, 256>>>();
    k_scan2<<<1, 512>>>();
    k_scan3<<<NBLK, 256>>>();
    k_fill<<<(EE + 255) / 256, 256>>>();
    k_gemm1<<<(NN / 4 + 7) / 8, 256>>>(x, W_shared);
    k_aggcsr<<<(NN + 7) / 8, 256>>>(b_shared, 0);   // t' -> h'
    k_aggcsr<<<(NN + 7) / 8, 256>>>(nullptr, 1);    // h' -> agg
    k_mlp<<<NN / 32, 256>>>(eps_c, eps_n, Wmc, bmc, Wmn, bmn, Wlc, blc, Wln, bln,
                            Wd1c, bd1c, Wd2c, bd2c, Wd1n, bd1n, Wd2n, bd2n,
                            omc, omn, olc, oln);
    k_decode<<<(EE + 255) / 256, 256>>>(oewc, oewn);
}